// round 16
// baseline (speedup 1.0000x reference)
#include <cuda_runtime.h>
#include <cuda_bf16.h>
#include <math.h>

// ---------------- problem constants ----------------
#define B_N   32
#define L_N   4096
#define C_N   96
#define GG_N  64
#define NW_N  2048
#define T_N   131072
#define HID_N 384

#define OUT0_ELEMS (T_N * C_N)
#define ATTN_ELEMS (NW_N * 3 * GG_N * GG_N)

#define SCALE_F 0.17677669529663687f  // 32^-0.5

// ---------------- scratch ----------------
__device__ float g_attn_fb[ATTN_ELEMS];  // fallback sink for attn probs

// fragment-packed bf16 weights: per (n8-tile, ks): 32 lanes x uint2
__device__ uint2 g_wqkv_p[36 * 6 * 32];      // N=288
__device__ uint2 g_wproj_p[12 * 6 * 32];     // N=96
__device__ uint2 g_w1_p[48 * 6 * 32];        // N=384
__device__ uint2 g_w2_p[4 * 12 * 6 * 32];    // 4 chunks, N=96 each

__device__ __forceinline__ unsigned packbf(float a, float b) {
    __nv_bfloat162 t = __floats2bfloat162_rn(a, b);
    return *(unsigned*)&t;
}

// jobs: qkv 6912, proj 2304, w1 9216, w2 9216  (total 27648)
__global__ void prep_weights(const float* __restrict__ wqkv,
                             const float* __restrict__ wproj,
                             const float* __restrict__ w1,
                             const float* __restrict__ w2) {
    int i = blockIdx.x * 256 + threadIdx.x;
    const float* src;
    uint2* dst;
    int ld, kbase = 0, idx;
    if (i < 6912)              { src = wqkv;  dst = g_wqkv_p;  ld = 288; idx = i; }
    else if (i < 9216)         { src = wproj; dst = g_wproj_p; ld = 96;  idx = i - 6912; }
    else if (i < 18432)        { src = w1;    dst = g_w1_p;    ld = 384; idx = i - 9216; }
    else                       {
        int j = i - 18432;
        int c = j / 2304;
        src = w2; dst = g_w2_p + c * 2304; ld = 96; kbase = c * 96; idx = j - c * 2304;
    }
    int q = idx >> 5, lane = idx & 31;
    int n8 = q / 6, ks = q - n8 * 6;
    int g = lane >> 2, tig = lane & 3;
    int n = n8 * 8 + g;
    int k0 = kbase + ks * 16 + tig * 2;
    uint2 v;
    v.x = packbf(src[(size_t)k0 * ld + n],       src[(size_t)(k0 + 1) * ld + n]);
    v.y = packbf(src[(size_t)(k0 + 8) * ld + n], src[(size_t)(k0 + 9) * ld + n]);
    dst[q * 32 + lane] = v;
}

__device__ __forceinline__ int win2tok(int m) {
    int w = m >> 6, t = m & 63;
    int b = w >> 6, rem = w & 63;
    int hy = rem >> 3, wx = rem & 7;
    int gy = t >> 3,  gx = t & 7;
    return b * L_N + (hy * 8 + gy) * 64 + (wx * 8 + gx);
}

__device__ __forceinline__ void mma16(float* c, const unsigned* a, const unsigned* b) {
    asm volatile(
        "mma.sync.aligned.m16n8k16.row.col.f32.bf16.bf16.f32 "
        "{%0,%1,%2,%3}, {%4,%5,%6,%7}, {%8,%9}, {%0,%1,%2,%3};\n"
        : "+f"(c[0]), "+f"(c[1]), "+f"(c[2]), "+f"(c[3])
        : "r"(a[0]), "r"(a[1]), "r"(a[2]), "r"(a[3]), "r"(b[0]), "r"(b[1]));
}

// ldmatrix: a-operand (16x16) in 1 instr; b-operand (16x8) in 1 instr
__device__ __forceinline__ void ldsm4(unsigned* r, const void* p) {
    unsigned addr = (unsigned)__cvta_generic_to_shared(p);
    asm volatile("ldmatrix.sync.aligned.m8n8.x4.shared.b16 {%0,%1,%2,%3}, [%4];"
                 : "=r"(r[0]), "=r"(r[1]), "=r"(r[2]), "=r"(r[3]) : "r"(addr));
}
__device__ __forceinline__ void ldsm2(unsigned* r, const void* p) {
    unsigned addr = (unsigned)__cvta_generic_to_shared(p);
    asm volatile("ldmatrix.sync.aligned.m8n8.x2.shared.b16 {%0,%1}, [%2];"
                 : "=r"(r[0]), "=r"(r[1]) : "r"(addr));
}

// unpack 8 bf16 (16B-aligned) into 8 floats via one LDS.128
__device__ __forceinline__ void load8bf(float* dst, const __nv_bfloat16* p) {
    uint4 u = *(const uint4*)p;
    __nv_bfloat162 b0 = *(__nv_bfloat162*)&u.x;
    __nv_bfloat162 b1 = *(__nv_bfloat162*)&u.y;
    __nv_bfloat162 b2 = *(__nv_bfloat162*)&u.z;
    __nv_bfloat162 b3 = *(__nv_bfloat162*)&u.w;
    dst[0] = __low2float(b0); dst[1] = __high2float(b0);
    dst[2] = __low2float(b1); dst[3] = __high2float(b1);
    dst[4] = __low2float(b2); dst[5] = __high2float(b2);
    dst[6] = __low2float(b3); dst[7] = __high2float(b3);
}

// ---------------- smem layout (bytes); row stride 104 bf16 for LDSM ----
// Os ALIASES As: As live phases 0-1 and 4a-4b; Os live phases 1.5-3
// (disjoint, separated by block-wide barriers). Total 53760 B -> 4 blocks/SM.
#define SM_AS  0        // 13312: As (stride 104) | Os (lepe+attn) | As (LN2)
#define SM_QS  13312    // 13312: Q scaled, stride 104 | Hs (MLP hidden chunk)
#define SM_KS  26624    // 13312: K, stride 104
#define SM_VT  39936    // 13824: V^T [c][t], stride 72
#define SM_TOT 53760

__global__ __launch_bounds__(256, 4)
void block_kernel(const float* __restrict__ x,
                  const float* __restrict__ bqkv,
                  const float* __restrict__ wl,
                  const float* __restrict__ bl,
                  const float* __restrict__ bproj,
                  const float* __restrict__ g1,
                  const float* __restrict__ bt1,
                  const float* __restrict__ g2,
                  const float* __restrict__ bt2,
                  const float* __restrict__ b1,
                  const float* __restrict__ b2,
                  float* __restrict__ out,
                  float* __restrict__ attn_out) {
    extern __shared__ char smraw[];
    __nv_bfloat16* As = (__nv_bfloat16*)(smraw + SM_AS);
    __nv_bfloat16* Os = (__nv_bfloat16*)(smraw + SM_AS);   // alias (disjoint life)
    __nv_bfloat16* Qs = (__nv_bfloat16*)(smraw + SM_QS);
    __nv_bfloat16* Hs = (__nv_bfloat16*)(smraw + SM_QS);   // alias (disjoint life)
    __nv_bfloat16* Ks = (__nv_bfloat16*)(smraw + SM_KS);
    __nv_bfloat16* Vt = (__nv_bfloat16*)(smraw + SM_VT);

    int w = blockIdx.x;
    int tid = threadIdx.x, lane = tid & 31, wid = tid >> 5;
    int g = lane >> 2, tig = lane & 3;
    int mw = (wid >> 1) * 16, wh = wid & 1;

    // ldmatrix per-lane offsets (elements)
    int arow = (lane & 7) + (lane & 8);           // 0..15
    int aoff104 = arow * 104 + ((lane & 16) ? 8 : 0);
    int boff104 = (lane & 7) * 104 + ((lane & 8) ? 8 : 0);
    int boff72  = (lane & 7) * 72  + ((lane & 8) ? 8 : 0);

    // ---- phase 0: LN1(x window rows) -> As bf16 ----
    #pragma unroll
    for (int r = 0; r < 8; r++) {
        int t = wid * 8 + r;
        const float* xr = x + (size_t)win2tok(w * 64 + t) * 96;
        float v0 = xr[lane], v1 = xr[lane + 32], v2 = xr[lane + 64];
        float s = v0 + v1 + v2;
        #pragma unroll
        for (int o = 16; o; o >>= 1) s += __shfl_xor_sync(~0u, s, o);
        float m = s * (1.f / 96.f);
        float d0 = v0 - m, d1 = v1 - m, d2 = v2 - m;
        float q = d0 * d0 + d1 * d1 + d2 * d2;
        #pragma unroll
        for (int o = 16; o; o >>= 1) q += __shfl_xor_sync(~0u, q, o);
        float rr = rsqrtf(q * (1.f / 96.f) + 1e-5f);
        As[t * 104 + lane]      = __float2bfloat16(d0 * rr * g1[lane]      + bt1[lane]);
        As[t * 104 + lane + 32] = __float2bfloat16(d1 * rr * g1[lane + 32] + bt1[lane + 32]);
        As[t * 104 + lane + 64] = __float2bfloat16(d2 * rr * g1[lane + 64] + bt1[lane + 64]);
    }
    __syncthreads();

    // ---- phase 1: QKV (a-frags hoisted via ldmatrix; b via LDG) ----
    {
        unsigned af[6][4];
        #pragma unroll
        for (int ks = 0; ks < 6; ks++)
            ldsm4(af[ks], As + mw * 104 + ks * 16 + aoff104);
        #pragma unroll
        for (int seg = 0; seg < 3; seg++) {
            int nw = wh * 48;
            float acc[6][4] = {};
            #pragma unroll
            for (int ks = 0; ks < 6; ks++) {
                #pragma unroll
                for (int nt = 0; nt < 6; nt++) {
                    int n8 = seg * 12 + wh * 6 + nt;
                    uint2 v = __ldg(&g_wqkv_p[(n8 * 6 + ks) * 32 + lane]);
                    mma16(acc[nt], af[ks], (const unsigned*)&v);
                }
            }
            #pragma unroll
            for (int nt = 0; nt < 6; nt++) {
                #pragma unroll
                for (int half = 0; half < 2; half++) {
                    int t = mw + g + half * 8;
                    int c = nw + nt * 8 + tig * 2;
                    float v0 = acc[nt][half * 2 + 0] + bqkv[seg * 96 + c];
                    float v1 = acc[nt][half * 2 + 1] + bqkv[seg * 96 + c + 1];
                    if (seg == 0) {
                        *(__nv_bfloat162*)&Qs[t * 104 + c] =
                            __floats2bfloat162_rn(v0 * SCALE_F, v1 * SCALE_F);
                    } else if (seg == 1) {
                        *(__nv_bfloat162*)&Ks[t * 104 + c] =
                            __floats2bfloat162_rn(v0, v1);
                    } else {
                        Vt[c * 72 + t]       = __float2bfloat16(v0);
                        Vt[(c + 1) * 72 + t] = __float2bfloat16(v1);
                    }
                }
            }
        }
    }
    __syncthreads();
    // As is now dead; Os (same region) becomes live.

    // ---- phase 1.5: LePE init: Os[t][d] = bf16(bl[d] + conv3x3(V_d)) ----
    #pragma unroll
    for (int j = 0; j < 3; j++) {
        int r = tid * 3 + j;
        int d = r >> 3, gy = r & 7;
        const float* wr = wl + d * 9;
        float w00 = wr[0], w01 = wr[1], w02 = wr[2];
        float w10 = wr[3], w11 = wr[4], w12 = wr[5];
        float w20 = wr[6], w21 = wr[7], w22 = wr[8];
        const __nv_bfloat16* vb = Vt + d * 72;
        float vt[8], vm[8], vbo[8];
        load8bf(vm, vb + gy * 8);
        if (gy > 0) {
            load8bf(vt, vb + (gy - 1) * 8);
        } else {
            for (int q2 = 0; q2 < 8; q2++) vt[q2] = 0.f;
        }
        if (gy < 7) {
            load8bf(vbo, vb + (gy + 1) * 8);
        } else {
            for (int q2 = 0; q2 < 8; q2++) vbo[q2] = 0.f;
        }
        float base = bl[d];
        #pragma unroll
        for (int gx = 0; gx < 8; gx++) {
            float o = base + vt[gx] * w01 + vm[gx] * w11 + vbo[gx] * w21;
            if (gx > 0) o += vt[gx - 1] * w00 + vm[gx - 1] * w10 + vbo[gx - 1] * w20;
            if (gx < 7) o += vt[gx + 1] * w02 + vm[gx + 1] * w12 + vbo[gx + 1] * w22;
            Os[(gy * 8 + gx) * 104 + d] = __float2bfloat16(o);
        }
    }
    __syncthreads();

    // ---- phase 2: attention, register-resident P (FA2-style) ----
    #pragma unroll
    for (int pass = 0; pass < 2; pass++) {
        int u = wid + pass * 8;
        if (u < 12) {
            int h = u >> 2, rb = u & 3;
            int h32 = h * 32, mw2 = rb * 16;
            unsigned qf[2][4];
            #pragma unroll
            for (int ks = 0; ks < 2; ks++)
                ldsm4(qf[ks], Qs + mw2 * 104 + h32 + ks * 16 + aoff104);
            float sacc[8][4] = {};
            #pragma unroll
            for (int nt = 0; nt < 8; nt++) {
                #pragma unroll
                for (int ks = 0; ks < 2; ks++) {
                    unsigned b[2];
                    ldsm2(b, Ks + (nt * 8) * 104 + h32 + ks * 16 + boff104);
                    mma16(sacc[nt], qf[ks], b);
                }
            }
            float m0 = -1e30f, m1 = -1e30f;
            #pragma unroll
            for (int nt = 0; nt < 8; nt++) {
                m0 = fmaxf(m0, fmaxf(sacc[nt][0], sacc[nt][1]));
                m1 = fmaxf(m1, fmaxf(sacc[nt][2], sacc[nt][3]));
            }
            m0 = fmaxf(m0, __shfl_xor_sync(~0u, m0, 1));
            m0 = fmaxf(m0, __shfl_xor_sync(~0u, m0, 2));
            m1 = fmaxf(m1, __shfl_xor_sync(~0u, m1, 1));
            m1 = fmaxf(m1, __shfl_xor_sync(~0u, m1, 2));
            float s0 = 0.f, s1 = 0.f;
            #pragma unroll
            for (int nt = 0; nt < 8; nt++) {
                sacc[nt][0] = __expf(sacc[nt][0] - m0);
                sacc[nt][1] = __expf(sacc[nt][1] - m0);
                sacc[nt][2] = __expf(sacc[nt][2] - m1);
                sacc[nt][3] = __expf(sacc[nt][3] - m1);
                s0 += sacc[nt][0] + sacc[nt][1];
                s1 += sacc[nt][2] + sacc[nt][3];
            }
            s0 += __shfl_xor_sync(~0u, s0, 1); s0 += __shfl_xor_sync(~0u, s0, 2);
            s1 += __shfl_xor_sync(~0u, s1, 1); s1 += __shfl_xor_sync(~0u, s1, 2);
            float inv0 = 1.f / s0, inv1 = 1.f / s1;
            float* ao = attn_out + (size_t)((w * 3 + h) * 64) * 64;
            #pragma unroll
            for (int nt = 0; nt < 8; nt++) {
                sacc[nt][0] *= inv0; sacc[nt][1] *= inv0;
                sacc[nt][2] *= inv1; sacc[nt][3] *= inv1;
                int c = nt * 8 + tig * 2;
                *(float2*)&ao[(size_t)(mw2 + g) * 64 + c] =
                    make_float2(sacc[nt][0], sacc[nt][1]);
                *(float2*)&ao[(size_t)(mw2 + g + 8) * 64 + c] =
                    make_float2(sacc[nt][2], sacc[nt][3]);
            }
            unsigned pa[4][4];
            #pragma unroll
            for (int kc = 0; kc < 4; kc++) {
                pa[kc][0] = packbf(sacc[2 * kc][0],     sacc[2 * kc][1]);
                pa[kc][1] = packbf(sacc[2 * kc][2],     sacc[2 * kc][3]);
                pa[kc][2] = packbf(sacc[2 * kc + 1][0], sacc[2 * kc + 1][1]);
                pa[kc][3] = packbf(sacc[2 * kc + 1][2], sacc[2 * kc + 1][3]);
            }
            float pacc[4][4] = {};
            #pragma unroll
            for (int nt = 0; nt < 4; nt++) {
                #pragma unroll
                for (int kc = 0; kc < 4; kc++) {
                    unsigned b[2];
                    ldsm2(b, Vt + (h32 + nt * 8) * 72 + kc * 16 + boff72);
                    mma16(pacc[nt], pa[kc], b);
                }
            }
            #pragma unroll
            for (int nt = 0; nt < 4; nt++) {
                #pragma unroll
                for (int half = 0; half < 2; half++) {
                    int t = mw2 + g + half * 8;
                    #pragma unroll
                    for (int ee = 0; ee < 2; ee++) {
                        int d = h32 + nt * 8 + tig * 2 + ee;
                        float prev = __bfloat162float(Os[t * 104 + d]);
                        Os[t * 104 + d] =
                            __float2bfloat16(prev + pacc[nt][half * 2 + ee]);
                    }
                }
            }
        }
    }
    __syncthreads();

    // ---- phase 3: proj + residual(x) -> x1 staged in out gmem ----
    {
        int nw = wh * 48;
        float acc[6][4] = {};
        unsigned of[6][4];
        #pragma unroll
        for (int ks = 0; ks < 6; ks++)
            ldsm4(of[ks], Os + mw * 104 + ks * 16 + aoff104);
        #pragma unroll
        for (int ks = 0; ks < 6; ks++) {
            #pragma unroll
            for (int nt = 0; nt < 6; nt++) {
                int n8 = wh * 6 + nt;
                uint2 v = __ldg(&g_wproj_p[(n8 * 6 + ks) * 32 + lane]);
                mma16(acc[nt], of[ks], (const unsigned*)&v);
            }
        }
        #pragma unroll
        for (int half = 0; half < 2; half++) {
            int t = mw + g + half * 8;
            int tok = win2tok(w * 64 + t);
            #pragma unroll
            for (int nt = 0; nt < 6; nt++) {
                int c = nw + nt * 8 + tig * 2;
                float2 xr = __ldg((const float2*)&x[(size_t)tok * 96 + c]);
                float v0 = acc[nt][half * 2 + 0] + bproj[c]     + xr.x;
                float v1 = acc[nt][half * 2 + 1] + bproj[c + 1] + xr.y;
                *(float2*)(out + (size_t)tok * 96 + c) = make_float2(v0, v1);
            }
        }
    }
    __syncthreads();
    // Os dead again; As (same region) becomes live for LN2.

    // ---- phase 4a: LN2 (x1 rows from out gmem) -> As ----
    #pragma unroll
    for (int r = 0; r < 8; r++) {
        int t = wid * 8 + r;
        const float* xr = out + (size_t)win2tok(w * 64 + t) * 96;
        float v0 = xr[lane], v1 = xr[lane + 32], v2 = xr[lane + 64];
        float s = v0 + v1 + v2;
        #pragma unroll
        for (int o = 16; o; o >>= 1) s += __shfl_xor_sync(~0u, s, o);
        float m = s * (1.f / 96.f);
        float d0 = v0 - m, d1 = v1 - m, d2 = v2 - m;
        float q = d0 * d0 + d1 * d1 + d2 * d2;
        #pragma unroll
        for (int o = 16; o; o >>= 1) q += __shfl_xor_sync(~0u, q, o);
        float rr = rsqrtf(q * (1.f / 96.f) + 1e-5f);
        As[t * 104 + lane]      = __float2bfloat16(d0 * rr * g2[lane]      + bt2[lane]);
        As[t * 104 + lane + 32] = __float2bfloat16(d1 * rr * g2[lane + 32] + bt2[lane + 32]);
        As[t * 104 + lane + 64] = __float2bfloat16(d2 * rr * g2[lane + 64] + bt2[lane + 64]);
    }
    __syncthreads();

    // ---- phase 4b: MLP chunks (Hs overlays dead Qs) ----
    float acc2[6][4] = {};
    int nw = wh * 48;
    for (int c = 0; c < 4; c++) {
        float accH[6][4] = {};
        {
            unsigned af[6][4];
            #pragma unroll
            for (int ks = 0; ks < 6; ks++)
                ldsm4(af[ks], As + mw * 104 + ks * 16 + aoff104);
            #pragma unroll
            for (int ks = 0; ks < 6; ks++) {
                #pragma unroll
                for (int nt = 0; nt < 6; nt++) {
                    int n8 = c * 12 + wh * 6 + nt;
                    uint2 v = __ldg(&g_w1_p[(n8 * 6 + ks) * 32 + lane]);
                    mma16(accH[nt], af[ks], (const unsigned*)&v);
                }
            }
        }
        // bias1 + exact GELU -> Hs
        #pragma unroll
        for (int half = 0; half < 2; half++) {
            int row = mw + g + half * 8;
            #pragma unroll
            for (int nt = 0; nt < 6; nt++) {
                int col = nw + nt * 8 + tig * 2;
                float v0 = accH[nt][half * 2 + 0] + b1[c * 96 + col];
                float v1 = accH[nt][half * 2 + 1] + b1[c * 96 + col + 1];
                v0 = 0.5f * v0 * (1.f + erff(v0 * 0.70710678118f));
                v1 = 0.5f * v1 * (1.f + erff(v1 * 0.70710678118f));
                *(__nv_bfloat162*)&Hs[row * 104 + col] = __floats2bfloat162_rn(v0, v1);
            }
        }
        __syncthreads();

        // acc2 += Hs @ W2c
        {
            unsigned hf[6][4];
            #pragma unroll
            for (int ks = 0; ks < 6; ks++)
                ldsm4(hf[ks], Hs + mw * 104 + ks * 16 + aoff104);
            #pragma unroll
            for (int ks = 0; ks < 6; ks++) {
                #pragma unroll
                for (int nt = 0; nt < 6; nt++) {
                    int n8 = wh * 6 + nt;
                    uint2 v = __ldg(&g_w2_p[c * 2304 + (n8 * 6 + ks) * 32 + lane]);
                    mma16(acc2[nt], hf[ks], (const unsigned*)&v);
                }
            }
        }
        __syncthreads();
    }

    // epilogue: out = x1(out gmem) + mlp + b2
    #pragma unroll
    for (int half = 0; half < 2; half++) {
        int t = mw + g + half * 8;
        int tok = win2tok(w * 64 + t);
        #pragma unroll
        for (int nt = 0; nt < 6; nt++) {
            int c = nw + nt * 8 + tig * 2;
            float2 x1r = __ldg((const float2*)&out[(size_t)tok * 96 + c]);
            float v0 = acc2[nt][half * 2 + 0] + b2[c]     + x1r.x;
            float v1 = acc2[nt][half * 2 + 1] + b2[c + 1] + x1r.y;
            *(float2*)(out + (size_t)tok * 96 + c) = make_float2(v0, v1);
        }
    }
}

// ---------------- launch ----------------
extern "C" void kernel_launch(void* const* d_in, const int* in_sizes, int n_in,
                              void* d_out, int out_size) {
    const float* x      = (const float*)d_in[0];
    const float* w_qkv  = (const float*)d_in[1];
    const float* b_qkv  = (const float*)d_in[2];
    const float* w_lepe = (const float*)d_in[3];
    const float* b_lepe = (const float*)d_in[4];
    const float* w_proj = (const float*)d_in[5];
    const float* b_proj = (const float*)d_in[6];
    const float* g1     = (const float*)d_in[7];
    const float* bt1    = (const float*)d_in[8];
    const float* g2     = (const float*)d_in[9];
    const float* bt2    = (const float*)d_in[10];
    const float* w_fc1  = (const float*)d_in[11];
    const float* b_fc1  = (const float*)d_in[12];
    const float* w_fc2  = (const float*)d_in[13];
    const float* b_fc2  = (const float*)d_in[14];

    float* out0 = (float*)d_out;

    float* pfb;
    cudaGetSymbolAddress((void**)&pfb, g_attn_fb);

    float* attn_out = (out_size >= OUT0_ELEMS + ATTN_ELEMS)
                        ? (out0 + OUT0_ELEMS) : pfb;

    cudaFuncSetAttribute(block_kernel,
                         cudaFuncAttributeMaxDynamicSharedMemorySize, SM_TOT);

    // 0. pack weights into mma b-fragment order
    prep_weights<<<108, 256>>>(w_qkv, w_proj, w_fc1, w_fc2);

    // 1. fully fused transformer block, one window per block
    block_kernel<<<NW_N, 256, SM_TOT>>>(x, b_qkv, w_lepe, b_lepe, b_proj,
                                        g1, bt1, g2, bt2, b_fc1, b_fc2,
                                        out0, attn_out);
}

// round 17
// speedup vs baseline: 1.2017x; 1.2017x over previous
#include <cuda_runtime.h>
#include <cuda_bf16.h>
#include <math.h>

// ---------------- problem constants ----------------
#define B_N   32
#define L_N   4096
#define C_N   96
#define GG_N  64
#define NW_N  2048
#define T_N   131072
#define HID_N 384

#define OUT0_ELEMS (T_N * C_N)
#define ATTN_ELEMS (NW_N * 3 * GG_N * GG_N)

#define SCALE_F 0.17677669529663687f  // 32^-0.5

// ---------------- scratch ----------------
__device__ float g_attn_fb[ATTN_ELEMS];  // fallback sink for attn probs

// fragment-packed bf16 weights: per (n8-tile, ks): 32 lanes x uint2
__device__ uint2 g_wqkv_p[36 * 6 * 32];      // N=288
__device__ uint2 g_wproj_p[12 * 6 * 32];     // N=96
__device__ uint2 g_w1_p[48 * 6 * 32];        // N=384
__device__ uint2 g_w2_p[4 * 12 * 6 * 32];    // 4 chunks, N=96 each

__device__ __forceinline__ unsigned packbf(float a, float b) {
    __nv_bfloat162 t = __floats2bfloat162_rn(a, b);
    return *(unsigned*)&t;
}

// streaming (evict-first) float2 store for write-once data
__device__ __forceinline__ void stcs2(float* p, float a, float b) {
    asm volatile("st.global.cs.v2.f32 [%0], {%1, %2};"
                 :: "l"(p), "f"(a), "f"(b) : "memory");
}

// jobs: qkv 6912, proj 2304, w1 9216, w2 9216  (total 27648)
__global__ void prep_weights(const float* __restrict__ wqkv,
                             const float* __restrict__ wproj,
                             const float* __restrict__ w1,
                             const float* __restrict__ w2) {
    int i = blockIdx.x * 256 + threadIdx.x;
    const float* src;
    uint2* dst;
    int ld, kbase = 0, idx;
    if (i < 6912)              { src = wqkv;  dst = g_wqkv_p;  ld = 288; idx = i; }
    else if (i < 9216)         { src = wproj; dst = g_wproj_p; ld = 96;  idx = i - 6912; }
    else if (i < 18432)        { src = w1;    dst = g_w1_p;    ld = 384; idx = i - 9216; }
    else                       {
        int j = i - 18432;
        int c = j / 2304;
        src = w2; dst = g_w2_p + c * 2304; ld = 96; kbase = c * 96; idx = j - c * 2304;
    }
    int q = idx >> 5, lane = idx & 31;
    int n8 = q / 6, ks = q - n8 * 6;
    int g = lane >> 2, tig = lane & 3;
    int n = n8 * 8 + g;
    int k0 = kbase + ks * 16 + tig * 2;
    uint2 v;
    v.x = packbf(src[(size_t)k0 * ld + n],       src[(size_t)(k0 + 1) * ld + n]);
    v.y = packbf(src[(size_t)(k0 + 8) * ld + n], src[(size_t)(k0 + 9) * ld + n]);
    dst[q * 32 + lane] = v;
}

__device__ __forceinline__ int win2tok(int m) {
    int w = m >> 6, t = m & 63;
    int b = w >> 6, rem = w & 63;
    int hy = rem >> 3, wx = rem & 7;
    int gy = t >> 3,  gx = t & 7;
    return b * L_N + (hy * 8 + gy) * 64 + (wx * 8 + gx);
}

__device__ __forceinline__ void mma16(float* c, const unsigned* a, const unsigned* b) {
    asm volatile(
        "mma.sync.aligned.m16n8k16.row.col.f32.bf16.bf16.f32 "
        "{%0,%1,%2,%3}, {%4,%5,%6,%7}, {%8,%9}, {%0,%1,%2,%3};\n"
        : "+f"(c[0]), "+f"(c[1]), "+f"(c[2]), "+f"(c[3])
        : "r"(a[0]), "r"(a[1]), "r"(a[2]), "r"(a[3]), "r"(b[0]), "r"(b[1]));
}

// ldmatrix: a-operand (16x16) in 1 instr; b-operand (16x8) in 1 instr
__device__ __forceinline__ void ldsm4(unsigned* r, const void* p) {
    unsigned addr = (unsigned)__cvta_generic_to_shared(p);
    asm volatile("ldmatrix.sync.aligned.m8n8.x4.shared.b16 {%0,%1,%2,%3}, [%4];"
                 : "=r"(r[0]), "=r"(r[1]), "=r"(r[2]), "=r"(r[3]) : "r"(addr));
}
__device__ __forceinline__ void ldsm2(unsigned* r, const void* p) {
    unsigned addr = (unsigned)__cvta_generic_to_shared(p);
    asm volatile("ldmatrix.sync.aligned.m8n8.x2.shared.b16 {%0,%1}, [%2];"
                 : "=r"(r[0]), "=r"(r[1]) : "r"(addr));
}

// unpack 8 bf16 (16B-aligned) into 8 floats via one LDS.128
__device__ __forceinline__ void load8bf(float* dst, const __nv_bfloat16* p) {
    uint4 u = *(const uint4*)p;
    __nv_bfloat162 b0 = *(__nv_bfloat162*)&u.x;
    __nv_bfloat162 b1 = *(__nv_bfloat162*)&u.y;
    __nv_bfloat162 b2 = *(__nv_bfloat162*)&u.z;
    __nv_bfloat162 b3 = *(__nv_bfloat162*)&u.w;
    dst[0] = __low2float(b0); dst[1] = __high2float(b0);
    dst[2] = __low2float(b1); dst[3] = __high2float(b1);
    dst[4] = __low2float(b2); dst[5] = __high2float(b2);
    dst[6] = __low2float(b3); dst[7] = __high2float(b3);
}

// ---------------- smem layout (bytes); row stride 104 bf16 for LDSM ----
#define SM_AS  0        // 13312: As (stride 104)
#define SM_QS  13312    // 13312: Q scaled, stride 104
#define SM_KS  26624    // 13312: K, stride 104
#define SM_VT  39936    // 13824: V^T [c][t], stride 72
#define SM_OS  53760    // 13312: lepe-init + attn-out (stride 104) / Hs
#define SM_TOT 67072

__global__ __launch_bounds__(256, 3)
void block_kernel(const float* __restrict__ x,
                  const float* __restrict__ bqkv,
                  const float* __restrict__ wl,
                  const float* __restrict__ bl,
                  const float* __restrict__ bproj,
                  const float* __restrict__ g1,
                  const float* __restrict__ bt1,
                  const float* __restrict__ g2,
                  const float* __restrict__ bt2,
                  const float* __restrict__ b1,
                  const float* __restrict__ b2,
                  float* __restrict__ out,
                  float* __restrict__ attn_out) {
    extern __shared__ char smraw[];
    __nv_bfloat16* As = (__nv_bfloat16*)(smraw + SM_AS);
    __nv_bfloat16* Qs = (__nv_bfloat16*)(smraw + SM_QS);
    __nv_bfloat16* Ks = (__nv_bfloat16*)(smraw + SM_KS);
    __nv_bfloat16* Vt = (__nv_bfloat16*)(smraw + SM_VT);
    __nv_bfloat16* Os = (__nv_bfloat16*)(smraw + SM_OS);
    __nv_bfloat16* Hs = (__nv_bfloat16*)(smraw + SM_OS);

    int w = blockIdx.x;
    int tid = threadIdx.x, lane = tid & 31, wid = tid >> 5;
    int g = lane >> 2, tig = lane & 3;
    int mw = (wid >> 1) * 16, wh = wid & 1;

    // ldmatrix per-lane offsets (elements)
    int arow = (lane & 7) + (lane & 8);           // 0..15
    int aoff104 = arow * 104 + ((lane & 16) ? 8 : 0);
    int boff104 = (lane & 7) * 104 + ((lane & 8) ? 8 : 0);
    int boff72  = (lane & 7) * 72  + ((lane & 8) ? 8 : 0);

    // ---- phase 0: LN1(x window rows) -> As bf16 ----
    #pragma unroll
    for (int r = 0; r < 8; r++) {
        int t = wid * 8 + r;
        const float* xr = x + (size_t)win2tok(w * 64 + t) * 96;
        float v0 = xr[lane], v1 = xr[lane + 32], v2 = xr[lane + 64];
        float s = v0 + v1 + v2;
        #pragma unroll
        for (int o = 16; o; o >>= 1) s += __shfl_xor_sync(~0u, s, o);
        float m = s * (1.f / 96.f);
        float d0 = v0 - m, d1 = v1 - m, d2 = v2 - m;
        float q = d0 * d0 + d1 * d1 + d2 * d2;
        #pragma unroll
        for (int o = 16; o; o >>= 1) q += __shfl_xor_sync(~0u, q, o);
        float rr = rsqrtf(q * (1.f / 96.f) + 1e-5f);
        As[t * 104 + lane]      = __float2bfloat16(d0 * rr * g1[lane]      + bt1[lane]);
        As[t * 104 + lane + 32] = __float2bfloat16(d1 * rr * g1[lane + 32] + bt1[lane + 32]);
        As[t * 104 + lane + 64] = __float2bfloat16(d2 * rr * g1[lane + 64] + bt1[lane + 64]);
    }
    __syncthreads();

    // ---- phase 1: QKV (a-frags hoisted via ldmatrix; b via LDG) ----
    {
        unsigned af[6][4];
        #pragma unroll
        for (int ks = 0; ks < 6; ks++)
            ldsm4(af[ks], As + mw * 104 + ks * 16 + aoff104);
        #pragma unroll
        for (int seg = 0; seg < 3; seg++) {
            int nw = wh * 48;
            float acc[6][4] = {};
            #pragma unroll
            for (int ks = 0; ks < 6; ks++) {
                #pragma unroll
                for (int nt = 0; nt < 6; nt++) {
                    int n8 = seg * 12 + wh * 6 + nt;
                    uint2 v = __ldg(&g_wqkv_p[(n8 * 6 + ks) * 32 + lane]);
                    mma16(acc[nt], af[ks], (const unsigned*)&v);
                }
            }
            #pragma unroll
            for (int nt = 0; nt < 6; nt++) {
                #pragma unroll
                for (int half = 0; half < 2; half++) {
                    int t = mw + g + half * 8;
                    int c = nw + nt * 8 + tig * 2;
                    float v0 = acc[nt][half * 2 + 0] + bqkv[seg * 96 + c];
                    float v1 = acc[nt][half * 2 + 1] + bqkv[seg * 96 + c + 1];
                    if (seg == 0) {
                        *(__nv_bfloat162*)&Qs[t * 104 + c] =
                            __floats2bfloat162_rn(v0 * SCALE_F, v1 * SCALE_F);
                    } else if (seg == 1) {
                        *(__nv_bfloat162*)&Ks[t * 104 + c] =
                            __floats2bfloat162_rn(v0, v1);
                    } else {
                        Vt[c * 72 + t]       = __float2bfloat16(v0);
                        Vt[(c + 1) * 72 + t] = __float2bfloat16(v1);
                    }
                }
            }
        }
    }
    __syncthreads();

    // ---- phase 1.5: LePE init: Os[t][d] = bf16(bl[d] + conv3x3(V_d)) ----
    #pragma unroll
    for (int j = 0; j < 3; j++) {
        int r = tid * 3 + j;
        int d = r >> 3, gy = r & 7;
        const float* wr = wl + d * 9;
        float w00 = wr[0], w01 = wr[1], w02 = wr[2];
        float w10 = wr[3], w11 = wr[4], w12 = wr[5];
        float w20 = wr[6], w21 = wr[7], w22 = wr[8];
        const __nv_bfloat16* vb = Vt + d * 72;
        float vt[8], vm[8], vbo[8];
        load8bf(vm, vb + gy * 8);
        if (gy > 0) {
            load8bf(vt, vb + (gy - 1) * 8);
        } else {
            for (int q2 = 0; q2 < 8; q2++) vt[q2] = 0.f;
        }
        if (gy < 7) {
            load8bf(vbo, vb + (gy + 1) * 8);
        } else {
            for (int q2 = 0; q2 < 8; q2++) vbo[q2] = 0.f;
        }
        float base = bl[d];
        #pragma unroll
        for (int gx = 0; gx < 8; gx++) {
            float o = base + vt[gx] * w01 + vm[gx] * w11 + vbo[gx] * w21;
            if (gx > 0) o += vt[gx - 1] * w00 + vm[gx - 1] * w10 + vbo[gx - 1] * w20;
            if (gx < 7) o += vt[gx + 1] * w02 + vm[gx + 1] * w12 + vbo[gx + 1] * w22;
            Os[(gy * 8 + gx) * 104 + d] = __float2bfloat16(o);
        }
    }
    __syncthreads();

    // ---- phase 2: attention, register-resident P (FA2-style) ----
    #pragma unroll
    for (int pass = 0; pass < 2; pass++) {
        int u = wid + pass * 8;
        if (u < 12) {
            int h = u >> 2, rb = u & 3;
            int h32 = h * 32, mw2 = rb * 16;
            unsigned qf[2][4];
            #pragma unroll
            for (int ks = 0; ks < 2; ks++)
                ldsm4(qf[ks], Qs + mw2 * 104 + h32 + ks * 16 + aoff104);
            float sacc[8][4] = {};
            #pragma unroll
            for (int nt = 0; nt < 8; nt++) {
                #pragma unroll
                for (int ks = 0; ks < 2; ks++) {
                    unsigned b[2];
                    ldsm2(b, Ks + (nt * 8) * 104 + h32 + ks * 16 + boff104);
                    mma16(sacc[nt], qf[ks], b);
                }
            }
            float m0 = -1e30f, m1 = -1e30f;
            #pragma unroll
            for (int nt = 0; nt < 8; nt++) {
                m0 = fmaxf(m0, fmaxf(sacc[nt][0], sacc[nt][1]));
                m1 = fmaxf(m1, fmaxf(sacc[nt][2], sacc[nt][3]));
            }
            m0 = fmaxf(m0, __shfl_xor_sync(~0u, m0, 1));
            m0 = fmaxf(m0, __shfl_xor_sync(~0u, m0, 2));
            m1 = fmaxf(m1, __shfl_xor_sync(~0u, m1, 1));
            m1 = fmaxf(m1, __shfl_xor_sync(~0u, m1, 2));
            float s0 = 0.f, s1 = 0.f;
            #pragma unroll
            for (int nt = 0; nt < 8; nt++) {
                sacc[nt][0] = __expf(sacc[nt][0] - m0);
                sacc[nt][1] = __expf(sacc[nt][1] - m0);
                sacc[nt][2] = __expf(sacc[nt][2] - m1);
                sacc[nt][3] = __expf(sacc[nt][3] - m1);
                s0 += sacc[nt][0] + sacc[nt][1];
                s1 += sacc[nt][2] + sacc[nt][3];
            }
            s0 += __shfl_xor_sync(~0u, s0, 1); s0 += __shfl_xor_sync(~0u, s0, 2);
            s1 += __shfl_xor_sync(~0u, s1, 1); s1 += __shfl_xor_sync(~0u, s1, 2);
            float inv0 = 1.f / s0, inv1 = 1.f / s1;
            float* ao = attn_out + (size_t)((w * 3 + h) * 64) * 64;
            #pragma unroll
            for (int nt = 0; nt < 8; nt++) {
                sacc[nt][0] *= inv0; sacc[nt][1] *= inv0;
                sacc[nt][2] *= inv1; sacc[nt][3] *= inv1;
                int c = nt * 8 + tig * 2;
                stcs2(&ao[(size_t)(mw2 + g) * 64 + c],     sacc[nt][0], sacc[nt][1]);
                stcs2(&ao[(size_t)(mw2 + g + 8) * 64 + c], sacc[nt][2], sacc[nt][3]);
            }
            unsigned pa[4][4];
            #pragma unroll
            for (int kc = 0; kc < 4; kc++) {
                pa[kc][0] = packbf(sacc[2 * kc][0],     sacc[2 * kc][1]);
                pa[kc][1] = packbf(sacc[2 * kc][2],     sacc[2 * kc][3]);
                pa[kc][2] = packbf(sacc[2 * kc + 1][0], sacc[2 * kc + 1][1]);
                pa[kc][3] = packbf(sacc[2 * kc + 1][2], sacc[2 * kc + 1][3]);
            }
            float pacc[4][4] = {};
            #pragma unroll
            for (int nt = 0; nt < 4; nt++) {
                #pragma unroll
                for (int kc = 0; kc < 4; kc++) {
                    unsigned b[2];
                    ldsm2(b, Vt + (h32 + nt * 8) * 72 + kc * 16 + boff72);
                    mma16(pacc[nt], pa[kc], b);
                }
            }
            #pragma unroll
            for (int nt = 0; nt < 4; nt++) {
                #pragma unroll
                for (int half = 0; half < 2; half++) {
                    int t = mw2 + g + half * 8;
                    #pragma unroll
                    for (int ee = 0; ee < 2; ee++) {
                        int d = h32 + nt * 8 + tig * 2 + ee;
                        float prev = __bfloat162float(Os[t * 104 + d]);
                        Os[t * 104 + d] =
                            __float2bfloat16(prev + pacc[nt][half * 2 + ee]);
                    }
                }
            }
        }
    }
    __syncthreads();

    // ---- phase 3: proj + residual(x) -> x1 staged in out gmem ----
    {
        int nw = wh * 48;
        float acc[6][4] = {};
        unsigned of[6][4];
        #pragma unroll
        for (int ks = 0; ks < 6; ks++)
            ldsm4(of[ks], Os + mw * 104 + ks * 16 + aoff104);
        #pragma unroll
        for (int ks = 0; ks < 6; ks++) {
            #pragma unroll
            for (int nt = 0; nt < 6; nt++) {
                int n8 = wh * 6 + nt;
                uint2 v = __ldg(&g_wproj_p[(n8 * 6 + ks) * 32 + lane]);
                mma16(acc[nt], of[ks], (const unsigned*)&v);
            }
        }
        #pragma unroll
        for (int half = 0; half < 2; half++) {
            int t = mw + g + half * 8;
            int tok = win2tok(w * 64 + t);
            #pragma unroll
            for (int nt = 0; nt < 6; nt++) {
                int c = nw + nt * 8 + tig * 2;
                float2 xr = __ldg((const float2*)&x[(size_t)tok * 96 + c]);
                float v0 = acc[nt][half * 2 + 0] + bproj[c]     + xr.x;
                float v1 = acc[nt][half * 2 + 1] + bproj[c + 1] + xr.y;
                *(float2*)(out + (size_t)tok * 96 + c) = make_float2(v0, v1);
            }
        }
    }
    __syncthreads();

    // ---- phase 4a: LN2 (x1 rows from out gmem) -> As ----
    #pragma unroll
    for (int r = 0; r < 8; r++) {
        int t = wid * 8 + r;
        const float* xr = out + (size_t)win2tok(w * 64 + t) * 96;
        float v0 = xr[lane], v1 = xr[lane + 32], v2 = xr[lane + 64];
        float s = v0 + v1 + v2;
        #pragma unroll
        for (int o = 16; o; o >>= 1) s += __shfl_xor_sync(~0u, s, o);
        float m = s * (1.f / 96.f);
        float d0 = v0 - m, d1 = v1 - m, d2 = v2 - m;
        float q = d0 * d0 + d1 * d1 + d2 * d2;
        #pragma unroll
        for (int o = 16; o; o >>= 1) q += __shfl_xor_sync(~0u, q, o);
        float rr = rsqrtf(q * (1.f / 96.f) + 1e-5f);
        As[t * 104 + lane]      = __float2bfloat16(d0 * rr * g2[lane]      + bt2[lane]);
        As[t * 104 + lane + 32] = __float2bfloat16(d1 * rr * g2[lane + 32] + bt2[lane + 32]);
        As[t * 104 + lane + 64] = __float2bfloat16(d2 * rr * g2[lane + 64] + bt2[lane + 64]);
    }
    __syncthreads();

    // ---- phase 4b: MLP chunks ----
    float acc2[6][4] = {};
    int nw = wh * 48;
    for (int c = 0; c < 4; c++) {
        float accH[6][4] = {};
        {
            unsigned af[6][4];
            #pragma unroll
            for (int ks = 0; ks < 6; ks++)
                ldsm4(af[ks], As + mw * 104 + ks * 16 + aoff104);
            #pragma unroll
            for (int ks = 0; ks < 6; ks++) {
                #pragma unroll
                for (int nt = 0; nt < 6; nt++) {
                    int n8 = c * 12 + wh * 6 + nt;
                    uint2 v = __ldg(&g_w1_p[(n8 * 6 + ks) * 32 + lane]);
                    mma16(accH[nt], af[ks], (const unsigned*)&v);
                }
            }
        }
        // bias1 + exact GELU -> Hs
        #pragma unroll
        for (int half = 0; half < 2; half++) {
            int row = mw + g + half * 8;
            #pragma unroll
            for (int nt = 0; nt < 6; nt++) {
                int col = nw + nt * 8 + tig * 2;
                float v0 = accH[nt][half * 2 + 0] + b1[c * 96 + col];
                float v1 = accH[nt][half * 2 + 1] + b1[c * 96 + col + 1];
                v0 = 0.5f * v0 * (1.f + erff(v0 * 0.70710678118f));
                v1 = 0.5f * v1 * (1.f + erff(v1 * 0.70710678118f));
                *(__nv_bfloat162*)&Hs[row * 104 + col] = __floats2bfloat162_rn(v0, v1);
            }
        }
        __syncthreads();

        // acc2 += Hs @ W2c
        {
            unsigned hf[6][4];
            #pragma unroll
            for (int ks = 0; ks < 6; ks++)
                ldsm4(hf[ks], Hs + mw * 104 + ks * 16 + aoff104);
            #pragma unroll
            for (int ks = 0; ks < 6; ks++) {
                #pragma unroll
                for (int nt = 0; nt < 6; nt++) {
                    int n8 = wh * 6 + nt;
                    uint2 v = __ldg(&g_w2_p[c * 2304 + (n8 * 6 + ks) * 32 + lane]);
                    mma16(acc2[nt], hf[ks], (const unsigned*)&v);
                }
            }
        }
        __syncthreads();
    }

    // epilogue: out = x1(out gmem) + mlp + b2  (terminal write: streaming)
    #pragma unroll
    for (int half = 0; half < 2; half++) {
        int t = mw + g + half * 8;
        int tok = win2tok(w * 64 + t);
        #pragma unroll
        for (int nt = 0; nt < 6; nt++) {
            int c = nw + nt * 8 + tig * 2;
            float2 x1r = __ldg((const float2*)&out[(size_t)tok * 96 + c]);
            float v0 = acc2[nt][half * 2 + 0] + b2[c]     + x1r.x;
            float v1 = acc2[nt][half * 2 + 1] + b2[c + 1] + x1r.y;
            stcs2(out + (size_t)tok * 96 + c, v0, v1);
        }
    }
}

// ---------------- launch ----------------
extern "C" void kernel_launch(void* const* d_in, const int* in_sizes, int n_in,
                              void* d_out, int out_size) {
    const float* x      = (const float*)d_in[0];
    const float* w_qkv  = (const float*)d_in[1];
    const float* b_qkv  = (const float*)d_in[2];
    const float* w_lepe = (const float*)d_in[3];
    const float* b_lepe = (const float*)d_in[4];
    const float* w_proj = (const float*)d_in[5];
    const float* b_proj = (const float*)d_in[6];
    const float* g1     = (const float*)d_in[7];
    const float* bt1    = (const float*)d_in[8];
    const float* g2     = (const float*)d_in[9];
    const float* bt2    = (const float*)d_in[10];
    const float* w_fc1  = (const float*)d_in[11];
    const float* b_fc1  = (const float*)d_in[12];
    const float* w_fc2  = (const float*)d_in[13];
    const float* b_fc2  = (const float*)d_in[14];

    float* out0 = (float*)d_out;

    float* pfb;
    cudaGetSymbolAddress((void**)&pfb, g_attn_fb);

    float* attn_out = (out_size >= OUT0_ELEMS + ATTN_ELEMS)
                        ? (out0 + OUT0_ELEMS) : pfb;

    cudaFuncSetAttribute(block_kernel,
                         cudaFuncAttributeMaxDynamicSharedMemorySize, SM_TOT);

    // 0. pack weights into mma b-fragment order
    prep_weights<<<108, 256>>>(w_qkv, w_proj, w_fc1, w_fc2);

    // 1. fully fused transformer block, one window per block
    block_kernel<<<NW_N, 256, SM_TOT>>>(x, b_qkv, w_lepe, b_lepe, b_proj,
                                        g1, bt1, g2, bt2, b_fc1, b_fc2,
                                        out0, attn_out);
}